// round 7
// baseline (speedup 1.0000x reference)
#include <cuda_runtime.h>
#include <cuda_bf16.h>
#include <math.h>

#define CS   1024
#define NH   16
#define HD   64
#define SEQ  1024
#define FINF 1e30f

// ---------------- scratch (device globals) ----------------
__device__ float g_g[SEQ * CS];
__device__ float g_z[(size_t)NH * SEQ * SEQ];

__device__ __align__(16) __nv_bfloat16 b_s_h[SEQ*CS],  b_s_l[SEQ*CS];
__device__ __align__(16) __nv_bfloat16 b_k_h[SEQ*CS],  b_k_l[SEQ*CS];
__device__ __align__(16) __nv_bfloat16 b_Wq_h[CS*CS],  b_Wq_l[CS*CS];
__device__ __align__(16) __nv_bfloat16 b_Wk_h[CS*CS],  b_Wk_l[CS*CS];
__device__ __align__(16) __nv_bfloat16 b_Wv_h[CS*CS],  b_Wv_l[CS*CS];
__device__ __align__(16) __nv_bfloat16 b_Wg_h[CS*CS],  b_Wg_l[CS*CS];
__device__ __align__(16) __nv_bfloat16 b_Wo_h[CS*CS],  b_Wo_l[CS*CS];
__device__ __align__(16) __nv_bfloat16 b_a_h[SEQ*CS],  b_a_l[SEQ*CS];
__device__ __align__(16) __nv_bfloat16 f_q_h[SEQ*CS],  f_q_l[SEQ*CS];
__device__ __align__(16) __nv_bfloat16 f_k_h[SEQ*CS],  f_k_l[SEQ*CS];
__device__ __align__(16) __nv_bfloat16 f_v_h[SEQ*CS],  f_v_l[SEQ*CS];

// ---------------- primitives ----------------
__device__ __forceinline__ void mma_bf16(float d[4], const unsigned a[4], const unsigned b[2]) {
    asm volatile(
        "mma.sync.aligned.m16n8k16.row.col.f32.bf16.bf16.f32 "
        "{%0,%1,%2,%3},{%4,%5,%6,%7},{%8,%9},{%0,%1,%2,%3};\n"
        : "+f"(d[0]), "+f"(d[1]), "+f"(d[2]), "+f"(d[3])
        : "r"(a[0]), "r"(a[1]), "r"(a[2]), "r"(a[3]), "r"(b[0]), "r"(b[1]));
}
__device__ __forceinline__ void ldsm4(unsigned r[4], unsigned addr) {
    asm volatile("ldmatrix.sync.aligned.m8n8.x4.shared.b16 {%0,%1,%2,%3}, [%4];\n"
                 : "=r"(r[0]), "=r"(r[1]), "=r"(r[2]), "=r"(r[3]) : "r"(addr));
}
__device__ __forceinline__ void ldsm2(unsigned r[2], unsigned addr) {
    asm volatile("ldmatrix.sync.aligned.m8n8.x2.shared.b16 {%0,%1}, [%2];\n"
                 : "=r"(r[0]), "=r"(r[1]) : "r"(addr));
}
__device__ __forceinline__ void ldsm2t(unsigned r[2], unsigned addr) {
    asm volatile("ldmatrix.sync.aligned.m8n8.x2.trans.shared.b16 {%0,%1}, [%2];\n"
                 : "=r"(r[0]), "=r"(r[1]) : "r"(addr));
}
__device__ __forceinline__ unsigned smem_u32(const void* p) {
    return (unsigned)__cvta_generic_to_shared(p);
}
__device__ __forceinline__ void cp16(unsigned dst, const void* src) {
    asm volatile("cp.async.cg.shared.global [%0], [%1], 16;\n" :: "r"(dst), "l"(src));
}
__device__ __forceinline__ void cp_commit() {
    asm volatile("cp.async.commit_group;\n" ::: "memory");
}
__device__ __forceinline__ void cp_wait1() {
    asm volatile("cp.async.wait_group 1;\n" ::: "memory");
}
__device__ __forceinline__ void cp_wait0() {
    asm volatile("cp.async.wait_group 0;\n" ::: "memory");
}
__device__ __forceinline__ unsigned packbf(float a, float b) {
    __nv_bfloat162 t = __floats2bfloat162_rn(a, b);
    return *(unsigned*)&t;
}
__device__ __forceinline__ void split1(float x, __nv_bfloat16& h, __nv_bfloat16& l) {
    h = __float2bfloat16_rn(x);
    l = __float2bfloat16_rn(x - __bfloat162float(h));
}
__device__ __forceinline__ void split4_store(float4 v, __nv_bfloat16* ph, __nv_bfloat16* pl) {
    __nv_bfloat16 h0,h1,h2,h3,l0,l1,l2,l3;
    split1(v.x,h0,l0); split1(v.y,h1,l1); split1(v.z,h2,l2); split1(v.w,h3,l3);
    __nv_bfloat162 hh0 = __halves2bfloat162(h0,h1), hh1 = __halves2bfloat162(h2,h3);
    __nv_bfloat162 ll0 = __halves2bfloat162(l0,l1), ll1 = __halves2bfloat162(l2,l3);
    uint2 hu; hu.x = *(unsigned*)&hh0; hu.y = *(unsigned*)&hh1;
    uint2 lu; lu.x = *(unsigned*)&ll0; lu.y = *(unsigned*)&ll1;
    *(uint2*)ph = hu; *(uint2*)pl = lu;
}
__device__ __forceinline__ void split2_store(float a, float b,
                                             __nv_bfloat16* ph, __nv_bfloat16* pl) {
    __nv_bfloat16 h0,h1,l0,l1;
    split1(a,h0,l0); split1(b,h1,l1);
    __nv_bfloat162 hh = __halves2bfloat162(h0,h1);
    __nv_bfloat162 ll = __halves2bfloat162(l0,l1);
    *(unsigned*)ph = *(unsigned*)&hh;
    *(unsigned*)pl = *(unsigned*)&ll;
}

// Kernel S: split the 7 fp32 source matrices into bf16 hi/lo
__global__ __launch_bounds__(256)
void split_kernel(const float* __restrict__ s,  const float* __restrict__ kin,
                  const float* __restrict__ Wq, const float* __restrict__ Wk,
                  const float* __restrict__ Wv, const float* __restrict__ Wg,
                  const float* __restrict__ Wo)
{
    const float* src; __nv_bfloat16 *dh, *dl;
    switch (blockIdx.y) {
        case 0:  src = s;   dh = b_s_h;  dl = b_s_l;  break;
        case 1:  src = kin; dh = b_k_h;  dl = b_k_l;  break;
        case 2:  src = Wq;  dh = b_Wq_h; dl = b_Wq_l; break;
        case 3:  src = Wk;  dh = b_Wk_h; dl = b_Wk_l; break;
        case 4:  src = Wv;  dh = b_Wv_h; dl = b_Wv_l; break;
        case 5:  src = Wg;  dh = b_Wg_h; dl = b_Wg_l; break;
        default: src = Wo;  dh = b_Wo_h; dl = b_Wo_l; break;
    }
    int i = (blockIdx.x * 256 + threadIdx.x) * 4;
    float4 v = *(const float4*)(src + i);
    split4_store(v, dh + i, dl + i);
}

// ---------------- bf16x3 GEMM core, 2-stage cp.async pipeline ----------------
#define LDT 40
#define GST (4*128*LDT)
#define GSMEM (2 * GST * 2)

__device__ __forceinline__ void mma_core(
    const __nv_bfloat16* __restrict__ Ah, const __nv_bfloat16* __restrict__ Al,
    const __nv_bfloat16* __restrict__ Bh, const __nv_bfloat16* __restrict__ Bl,
    int m0, int n0, float acc[4][4][4])
{
    extern __shared__ __nv_bfloat16 gsm[];

    const int tid  = threadIdx.x;
    const int lane = tid & 31;
    const int warp = tid >> 5;
    const int wm   = warp >> 2;
    const int wn   = warp & 3;

    #pragma unroll
    for (int mt = 0; mt < 4; mt++)
        #pragma unroll
        for (int nt = 0; nt < 4; nt++)
            #pragma unroll
            for (int u = 0; u < 4; u++) acc[mt][nt][u] = 0.f;

    const int r0 = tid >> 2,         c0 = (tid & 3) * 8;
    const int r1 = (tid + 256) >> 2;

    const unsigned ub = smem_u32(gsm);
    const unsigned oAl = 128*LDT*2, oBh = 2*128*LDT*2, oBl = 3*128*LDT*2;

    const int amat = lane >> 3, arow = lane & 7;
    const int a_r  = wm * 64 + (amat & 1) * 8 + arow;
    const int a_c  = (amat >> 1) * 8;
    const int b_r  = wn * 32 + arow;
    const int b_c  = ((lane >> 3) & 1) * 8;

    {
        size_t a0 = (size_t)(m0 + r0) * CS + c0, a1 = (size_t)(m0 + r1) * CS + c0;
        size_t b0 = (size_t)(n0 + r0) * CS + c0, b1 = (size_t)(n0 + r1) * CS + c0;
        unsigned s0o = (unsigned)(r0*LDT + c0) * 2, s1o = (unsigned)(r1*LDT + c0) * 2;
        cp16(ub + s0o,       Ah + a0); cp16(ub + s1o,       Ah + a1);
        cp16(ub + oAl + s0o, Al + a0); cp16(ub + oAl + s1o, Al + a1);
        cp16(ub + oBh + s0o, Bh + b0); cp16(ub + oBh + s1o, Bh + b1);
        cp16(ub + oBl + s0o, Bl + b0); cp16(ub + oBl + s1o, Bl + b1);
        cp_commit();
    }

    for (int it = 0; it < 32; it++) {
        const int k0 = it * 32;
        const bool more = (k0 + 32 < CS);
        if (more) {
            const int kn = k0 + 32;
            const unsigned sb = ub + ((it + 1) & 1) * (GST * 2);
            size_t a0 = (size_t)(m0 + r0) * CS + kn + c0, a1 = (size_t)(m0 + r1) * CS + kn + c0;
            size_t b0 = (size_t)(n0 + r0) * CS + kn + c0, b1 = (size_t)(n0 + r1) * CS + kn + c0;
            unsigned s0o = (unsigned)(r0*LDT + c0) * 2, s1o = (unsigned)(r1*LDT + c0) * 2;
            cp16(sb + s0o,       Ah + a0); cp16(sb + s1o,       Ah + a1);
            cp16(sb + oAl + s0o, Al + a0); cp16(sb + oAl + s1o, Al + a1);
            cp16(sb + oBh + s0o, Bh + b0); cp16(sb + oBh + s1o, Bh + b1);
            cp16(sb + oBl + s0o, Bl + b0); cp16(sb + oBl + s1o, Bl + b1);
            cp_commit();
            cp_wait1();
        } else {
            cp_wait0();
        }
        __syncthreads();

        const unsigned sb = ub + (it & 1) * (GST * 2);
        #pragma unroll
        for (int ks = 0; ks < 32; ks += 16) {
            unsigned afh[4][4], afl[4][4], bfh[4][2], bfl[4][2];
            #pragma unroll
            for (int mt = 0; mt < 4; mt++) {
                unsigned off = (unsigned)((a_r + mt*16) * LDT + ks + a_c) * 2;
                ldsm4(afh[mt], sb + off);
                ldsm4(afl[mt], sb + oAl + off);
            }
            #pragma unroll
            for (int nt = 0; nt < 4; nt++) {
                unsigned off = (unsigned)((b_r + nt*8) * LDT + ks + b_c) * 2;
                ldsm2(bfh[nt], sb + oBh + off);
                ldsm2(bfl[nt], sb + oBl + off);
            }
            #pragma unroll
            for (int mt = 0; mt < 4; mt++)
                #pragma unroll
                for (int nt = 0; nt < 4; nt++) {
                    mma_bf16(acc[mt][nt], afh[mt], bfh[nt]);
                    mma_bf16(acc[mt][nt], afh[mt], bfl[nt]);
                    mma_bf16(acc[mt][nt], afl[mt], bfh[nt]);
                }
        }
        __syncthreads();
    }
}

// Kernel 1: projections.  z: 0=q(+bq)->f_q, 1=k->f_k, 2=v->f_v, 3=g(sigmoid)->g_g fp32
__global__ __launch_bounds__(256)
void proj_mma(const float* __restrict__ bq)
{
    const __nv_bfloat16 *Ah, *Al, *Bh, *Bl;
    __nv_bfloat16 *OH = nullptr, *OL = nullptr;
    const float* bias = nullptr;
    switch (blockIdx.z) {
        case 0:  Ah=b_s_h; Al=b_s_l; Bh=b_Wq_h; Bl=b_Wq_l; OH=f_q_h; OL=f_q_l; bias=bq; break;
        case 1:  Ah=b_k_h; Al=b_k_l; Bh=b_Wk_h; Bl=b_Wk_l; OH=f_k_h; OL=f_k_l; break;
        case 2:  Ah=b_k_h; Al=b_k_l; Bh=b_Wv_h; Bl=b_Wv_l; OH=f_v_h; OL=f_v_l; break;
        default: Ah=b_s_h; Al=b_s_l; Bh=b_Wg_h; Bl=b_Wg_l; break;
    }
    const int m0 = blockIdx.y * 128, n0 = blockIdx.x * 128;
    float acc[4][4][4];
    mma_core(Ah, Al, Bh, Bl, m0, n0, acc);

    const int lane = threadIdx.x & 31, warp = threadIdx.x >> 5;
    const int wm = warp >> 2, wn = warp & 3;
    const int lr = lane >> 2, lc = (lane & 3) * 2;
    #pragma unroll
    for (int mt = 0; mt < 4; mt++)
        #pragma unroll
        for (int nt = 0; nt < 4; nt++) {
            int row = m0 + wm*64 + mt*16 + lr;
            int col = n0 + wn*32 + nt*8 + lc;
            float v0 = acc[mt][nt][0], v1 = acc[mt][nt][1];
            float v2 = acc[mt][nt][2], v3 = acc[mt][nt][3];
            if (bias) { float b0_ = bias[col], b1_ = bias[col+1];
                        v0 += b0_; v1 += b1_; v2 += b0_; v3 += b1_; }
            if (blockIdx.z == 3) {
                v0 = 1.0f/(1.0f+__expf(-v0)); v1 = 1.0f/(1.0f+__expf(-v1));
                v2 = 1.0f/(1.0f+__expf(-v2)); v3 = 1.0f/(1.0f+__expf(-v3));
                *(float2*)&g_g[(size_t)row*CS + col]     = make_float2(v0, v1);
                *(float2*)&g_g[(size_t)(row+8)*CS + col] = make_float2(v2, v3);
            } else {
                split2_store(v0, v1, OH + (size_t)row*CS + col,     OL + (size_t)row*CS + col);
                split2_store(v2, v3, OH + (size_t)(row+8)*CS + col, OL + (size_t)(row+8)*CS + col);
            }
        }
}

// Kernel 6: out = (g*o) @ Wo^T
__global__ __launch_bounds__(256)
void out_mma(float* __restrict__ out)
{
    const int m0 = blockIdx.y * 128, n0 = blockIdx.x * 128;
    float acc[4][4][4];
    mma_core(b_a_h, b_a_l, b_Wo_h, b_Wo_l, m0, n0, acc);

    const int lane = threadIdx.x & 31, warp = threadIdx.x >> 5;
    const int wm = warp >> 2, wn = warp & 3;
    const int lr = lane >> 2, lc = (lane & 3) * 2;
    #pragma unroll
    for (int mt = 0; mt < 4; mt++)
        #pragma unroll
        for (int nt = 0; nt < 4; nt++) {
            int row = m0 + wm*64 + mt*16 + lr;
            int col = n0 + wn*32 + nt*8 + lc;
            *(float2*)&out[(size_t)row*CS + col]     = make_float2(acc[mt][nt][0], acc[mt][nt][1]);
            *(float2*)&out[(size_t)(row+8)*CS + col] = make_float2(acc[mt][nt][2], acc[mt][nt][3]);
        }
}

// ---------------- zbias on tensor cores ----------------
// z[h, p] = sum_c bias[p, c] * Wz[c, h] + (1-mask[j])*(-1e6),  p = i*1024+j
// Per block: 256 pairs x 16 h, K=128 in 4 chunks of 32.
// bias chunk split to bf16 hi/lo in registers -> smem -> bf16x3 mma.
#define ZLA 40      // A smem stride (32 + 8)
#define ZLB 136     // WzT smem stride (128 + 8), 272B = 16B-aligned
#define ZSP 260     // epilogue transpose stride (floats)
#define ZSMEM ((2*256*ZLA + 2*16*ZLB) * 2)

__global__ __launch_bounds__(256)
void zbias_mma(const float* __restrict__ bias, const float* __restrict__ mask,
               const float* __restrict__ Wz)
{
    extern __shared__ __nv_bfloat16 zsm[];
    __nv_bfloat16* sah = zsm;                 // [256][ZLA]
    __nv_bfloat16* sal = sah + 256*ZLA;
    __nv_bfloat16* swh = sal + 256*ZLA;       // [16][ZLB]
    __nv_bfloat16* swl = swh + 16*ZLB;

    const int tid  = threadIdx.x;
    const int lane = tid & 31;
    const int warp = tid >> 5;
    const long p0  = (long)blockIdx.x * 256;

    // build WzT bf16 hi/lo: swh[h][c] = hi(Wz[c*16+h])
    for (int e = tid; e < 2048; e += 256) {
        int c = e >> 4, h = e & 15;
        __nv_bfloat16 hh, ll;
        split1(Wz[e], hh, ll);
        swh[h*ZLB + c] = hh;
        swl[h*ZLB + c] = ll;
    }

    float acc[2][2][4];
    #pragma unroll
    for (int mt = 0; mt < 2; mt++)
        #pragma unroll
        for (int nt = 0; nt < 2; nt++)
            #pragma unroll
            for (int u = 0; u < 4; u++) acc[mt][nt][u] = 0.f;

    const int amat = lane >> 3, arow = lane & 7;
    const int a_r = warp*32 + (amat & 1) * 8 + arow;   // + mt*16
    const int a_c = (amat >> 1) * 8;
    const int b_r = arow;                               // + nt*8
    const int b_c = ((lane >> 3) & 1) * 8;

    const unsigned uah = smem_u32(sah), ual = smem_u32(sal);
    const unsigned uwh = smem_u32(swh), uwl = smem_u32(swl);

    for (int cb = 0; cb < 4; cb++) {
        __syncthreads();
        // stage bias chunk: 256 pairs x 32 c, split in registers
        #pragma unroll
        for (int r = 0; r < 8; r++) {
            int f = tid + r * 256;
            int pair = f >> 3, cq = f & 7;
            float4 v = *(const float4*)&bias[(p0 + pair) * 128 + cb*32 + cq*4];
            split4_store(v, &sah[pair*ZLA + cq*4], &sal[pair*ZLA + cq*4]);
        }
        __syncthreads();
        #pragma unroll
        for (int ks = 0; ks < 32; ks += 16) {
            unsigned ah[2][4], al[2][4], bh[2][2], bl[2][2];
            #pragma unroll
            for (int mt = 0; mt < 2; mt++) {
                unsigned off = (unsigned)((a_r + mt*16) * ZLA + ks + a_c) * 2;
                ldsm4(ah[mt], uah + off);
                ldsm4(al[mt], ual + off);
            }
            #pragma unroll
            for (int nt = 0; nt < 2; nt++) {
                unsigned off = (unsigned)((b_r + nt*8) * ZLB + cb*32 + ks + b_c) * 2;
                ldsm2(bh[nt], uwh + off);
                ldsm2(bl[nt], uwl + off);
            }
            #pragma unroll
            for (int mt = 0; mt < 2; mt++)
                #pragma unroll
                for (int nt = 0; nt < 2; nt++) {
                    mma_bf16(acc[mt][nt], ah[mt], bh[nt]);
                    mma_bf16(acc[mt][nt], ah[mt], bl[nt]);
                    mma_bf16(acc[mt][nt], al[mt], bh[nt]);
                }
        }
    }
    __syncthreads();

    // transpose through smem for coalesced per-head writes
    float* szT = (float*)zsm;     // [16][ZSP] overlay (16.6KB <= sah region 20.5KB)
    const int lr = lane >> 2, t4 = lane & 3;
    #pragma unroll
    for (int mt = 0; mt < 2; mt++)
        #pragma unroll
        for (int nt = 0; nt < 2; nt++) {
            int pr = warp*32 + mt*16 + lr;
            int hc = nt*8 + t4*2;
            szT[hc*ZSP + pr]         = acc[mt][nt][0];
            szT[(hc+1)*ZSP + pr]     = acc[mt][nt][1];
            szT[hc*ZSP + pr + 8]     = acc[mt][nt][2];
            szT[(hc+1)*ZSP + pr + 8] = acc[mt][nt][3];
        }
    __syncthreads();

    const int j0 = (int)(p0 & (SEQ - 1));
    #pragma unroll
    for (int r = 0; r < 4; r++) {
        int f = tid + r * 256;           // 0..1023
        int h = f >> 6;                  // 64 float4 per head
        int seg = (f & 63) * 4;
        const float* src = szT + h*ZSP + seg;
        float4 o;
        o.x = src[0] + (1.0f - mask[j0 + seg + 0]) * (-1000000.0f);
        o.y = src[1] + (1.0f - mask[j0 + seg + 1]) * (-1000000.0f);
        o.z = src[2] + (1.0f - mask[j0 + seg + 2]) * (-1000000.0f);
        o.w = src[3] + (1.0f - mask[j0 + seg + 3]) * (-1000000.0f);
        *(float4*)&g_z[((long)h << 20) + p0 + seg] = o;
    }
}

// ---------------- flash attention v3 ----------------
// BI=32 q-rows, 256 threads (8 warps: wm 2 row-groups x wj 4 j-quarters),
// single-stage kv, sized for 2 blocks/SM (regs 22K/blk, smem 81KB/blk).
#define BI 32
#define LQ 72
#define FKV (4 * 128 * LQ)                 // halves (kh,kl,vh,vl)
#define FSMEM ((2*BI*LQ + FKV) * 2)        // bytes

__global__ __launch_bounds__(256)
void flash_kernel()
{
    extern __shared__ __nv_bfloat16 fsm[];
    __nv_bfloat16* sqh = fsm;
    __nv_bfloat16* sql = sqh + BI*LQ;
    __nv_bfloat16* kvb = sql + BI*LQ;
    float* cO = (float*)kvb;               // end-of-loop combine overlay

    __shared__ float cm[2][4][16];
    __shared__ float cl[2][4][16];

    const int h  = blockIdx.y;
    const int i0 = blockIdx.x * BI;
    const int tid  = threadIdx.x;
    const int lane = tid & 31;
    const int warp = tid >> 5;
    const int wm = warp >> 2, wj = warp & 3;
    const int lr = lane >> 2, t4 = lane & 3;

    // q tile: 32 x 64 hi/lo; 256 uint4 slots per array, 1 per thread
    {
        int r = tid >> 3, cc = (tid & 7) * 8;
        *(uint4*)&sqh[r*LQ + cc] = *(const uint4*)&f_q_h[(size_t)(i0+r)*CS + h*HD + cc];
        *(uint4*)&sql[r*LQ + cc] = *(const uint4*)&f_q_l[(size_t)(i0+r)*CS + h*HD + cc];
    }

    const unsigned uq  = smem_u32(sqh);
    const unsigned uql = smem_u32(sql);
    const unsigned ukv = smem_u32(kvb);
    const unsigned oKl = 128*LQ*2, oVh = 2*128*LQ*2, oVl = 3*128*LQ*2;

    const unsigned qoff = (unsigned)((wm*16 + (lane & 15)) * LQ + (lane >> 4) * 8) * 2;
    const unsigned koff = (unsigned)((wj*32 + (lane & 7)) * LQ + ((lane >> 3) & 1) * 8) * 2;
    const unsigned voff = (unsigned)((wj*32 + (lane & 7) + ((lane >> 3) & 1) * 8) * LQ) * 2;

    float m0 = -FINF, m1 = -FINF, l0 = 0.f, l1 = 0.f;
    float oac[8][4];
    #pragma unroll
    for (int d = 0; d < 8; d++)
        #pragma unroll
        for (int u = 0; u < 4; u++) oac[d][u] = 0.f;

    const float* Zbase = g_z + ((long)h << 20)
                       + (long)(i0 + wm*16 + lr) * SEQ + wj*32 + t4*2;

    for (int jt = 0; jt < 8; jt++) {
        // async-load k/v tile (hi+lo): 1024 slots per array, 4 per thread
        #pragma unroll
        for (int i = 0; i < 4; i++) {
            int u = tid + i*256;
            int r = u >> 3, cc = (u & 7) * 8;
            unsigned so = (unsigned)(r*LQ + cc) * 2;
            size_t go = (size_t)(jt*128 + r) * CS + h*HD + cc;
            cp16(ukv + so,       f_k_h + go);
            cp16(ukv + oKl + so, f_k_l + go);
            cp16(ukv + oVh + so, f_v_h + go);
            cp16(ukv + oVl + so, f_v_l + go);
        }
        cp_commit();
        cp_wait0();
        __syncthreads();

        // ---- S = q·k^T over warp's 16 x 32 slice (bf16x3) ----
        float sa[4][4];
        #pragma unroll
        for (int nt = 0; nt < 4; nt++)
            #pragma unroll
            for (int u = 0; u < 4; u++) sa[nt][u] = 0.f;

        #pragma unroll
        for (int ks = 0; ks < 64; ks += 16) {
            unsigned ah[4], al[4];
            ldsm4(ah, uq  + qoff + ks*2);
            ldsm4(al, uql + qoff + ks*2);
            #pragma unroll
            for (int nt = 0; nt < 4; nt++) {
                unsigned bh[2], bl[2];
                unsigned off = koff + (unsigned)(nt*8*LQ + ks) * 2;
                ldsm2(bh, ukv + off);
                ldsm2(bl, ukv + oKl + off);
                mma_bf16(sa[nt], ah, bh);
                mma_bf16(sa[nt], ah, bl);
                mma_bf16(sa[nt], al, bh);
            }
        }

        // ---- scale + z, online softmax (per warp, over its 32 j) ----
        const float* Zt = Zbase + jt * 128;
        float mx0 = -FINF, mx1 = -FINF;
        #pragma unroll
        for (int nt = 0; nt < 4; nt++) {
            float2 z0 = *(const float2*)(Zt + nt*8);
            float2 z1 = *(const float2*)(Zt + 8*SEQ + nt*8);
            sa[nt][0] = sa[nt][0]*0.125f + z0.x;
            sa[nt][1] = sa[nt][1]*0.125f + z0.y;
            sa[nt][2] = sa[nt][2]*0.125f + z1.x;
            sa[nt][3] = sa[nt][3]*0.125f + z1.y;
            mx0 = fmaxf(mx0, fmaxf(sa[nt][0], sa[nt][1]));
            mx1 = fmaxf(mx1, fmaxf(sa[nt][2], sa[nt][3]));
        }
        mx0 = fmaxf(mx0, __shfl_xor_sync(0xffffffffu, mx0, 1));
        mx0 = fmaxf(mx0, __shfl_xor_sync(0xffffffffu, mx0, 2));
        mx1 = fmaxf(mx1, __shfl_xor_sync(0xffffffffu, mx1, 1));
        mx1 = fmaxf(mx1, __shfl_xor_sync(0xffffffffu, mx1, 2));

        float mn0 = fmaxf(m0, mx0), mn1 = fmaxf(m1, mx1);
        float fa0 = __expf(m0 - mn0), fa1 = __expf(m1 - mn1);
        m0 = mn0; m1 = mn1;

        float sum0 = 0.f, sum1 = 0.f;
        #pragma unroll
        for (int nt = 0; nt < 4; nt++) {
            sa[nt][0] = __expf(sa[nt][0] - mn0);
            sa[nt][1] = __expf(sa[nt][1] - mn0);
            sa[nt][2] = __expf(sa[nt][2] - mn1);
            sa[nt][3] = __expf(sa[nt][3] - mn1);
            sum0 += sa[nt][0] + sa[nt][1];
            sum1 += sa[nt][2] + sa[nt][3];
        }
        sum0 += __shfl_xor_sync(0xffffffffu, sum0, 1);
        sum0 += __shfl_xor_sync(0xffffffffu, sum0, 2);
        sum1 += __shfl_xor_sync(0xffffffffu, sum1, 1);
        sum1 += __shfl_xor_sync(0xffffffffu, sum1, 2);
        l0 = l0 * fa0 + sum0;
        l1 = l1 * fa1 + sum1;

        #pragma unroll
        for (int d = 0; d < 8; d++) {
            oac[d][0] *= fa0; oac[d][1] *= fa0;
            oac[d][2] *= fa1; oac[d][3] *= fa1;
        }

        // ---- O += P·V over warp's 32 j (bf16x3) ----
        #pragma unroll
        for (int kt = 0; kt < 2; kt++) {
            float p00 = sa[2*kt][0],   p01 = sa[2*kt][1];
            float p02 = sa[2*kt][2],   p03 = sa[2*kt][3];
            float p10 = sa[2*kt+1][0], p11 = sa[2*kt+1][1];
            float p12 = sa[2*kt+1][2], p13 = sa[2*kt+1][3];

            unsigned pah[4], pal[4];
            pah[0] = packbf(p00, p01); pah[1] = packbf(p02, p03);
            pah[2] = packbf(p10, p11); pah[3] = packbf(p12, p13);
            {
                __nv_bfloat162 t0 = *(__nv_bfloat162*)&pah[0];
                __nv_bfloat162 t1 = *(__nv_bfloat162*)&pah[1];
                __nv_bfloat162 t2 = *(__nv_bfloat162*)&pah[2];
                __nv_bfloat162 t3 = *(__nv_bfloat162*)&pah[3];
                pal[0] = packbf(p00 - __bfloat162float(t0.x), p01 - __bfloat162float(t0.y));
                pal[1] = packbf(p02 - __bfloat162float(t1.x), p03 - __bfloat162float(t1.y));
                pal[2] = packbf(p10 - __bfloat162float(t2.x), p11 - __bfloat162float(t2.y));
                pal[3] = packbf(p12 - __bfloat162float(t3.x), p13 - __bfloat162float(t3.y));
            }

            #pragma unroll
            for (int dnt = 0; dnt < 8; dnt++) {
                unsigned bh[2], bl[2];
                unsigned off = voff + (unsigned)(kt*16*LQ + dnt*8) * 2;
                ldsm2t(bh, ukv + oVh + off);
                ldsm2t(bl, ukv + oVl + off);
                mma_bf16(oac[dnt], pah, bh);
                mma_bf16(oac[dnt], pah, bl);
                mma_bf16(oac[dnt], pal, bh);
            }
        }
        __syncthreads();
    }

    // ---- merge the 4 j-quarter partials via smem (overlay on kv region) ----
    {
        float* myO = cO + (size_t)((wm*4 + wj) * 16) * 68;
        #pragma unroll
        for (int dnt = 0; dnt < 8; dnt++) {
            int c = dnt*8 + t4*2;
            myO[lr*68 + c]       = oac[dnt][0];
            myO[lr*68 + c + 1]   = oac[dnt][1];
            myO[(lr+8)*68 + c]   = oac[dnt][2];
            myO[(lr+8)*68 + c+1] = oac[dnt][3];
        }
        if (t4 == 0) {
            cm[wm][wj][lr] = m0;   cl[wm][wj][lr] = l0;
            cm[wm][wj][lr+8] = m1; cl[wm][wj][lr+8] = l1;
        }
    }
    __syncthreads();

    // warp (wm, wj) combines rows of group wm, d-cols [wj*16, wj*16+16)
    {
        const int row = lane >> 1;
        const int db  = wj*16 + (lane & 1) * 8;
        float e[4], M = -FINF;
        #pragma unroll
        for (int w = 0; w < 4; w++) M = fmaxf(M, cm[wm][w][row]);
        float L = 0.f;
        #pragma unroll
        for (int w = 0; w < 4; w++) {
            e[w] = __expf(cm[wm][w][row] - M);
            L += cl[wm][w][row] * e[w];
        }
        const float invL = 1.0f / L;
        const int grow = i0 + wm*16 + row;
        const size_t gbase = (size_t)grow * CS + h*HD;

        #pragma unroll
        for (int p = 0; p < 4; p++) {
            int d = db + p*2;
            float o0 = 0.f, o1 = 0.f;
            #pragma unroll
            for (int w = 0; w < 4; w++) {
                const float* src = cO + (size_t)((wm*4 + w) * 16 + row) * 68 + d;
                o0 += src[0] * e[w];
                o1 += src[1] * e[w];
            }
            float2 gv = *(const float2*)&g_g[gbase + d];
            split2_store(o0 * invL * gv.x, o1 * invL * gv.y,
                         b_a_h + gbase + d, b_a_l + gbase + d);
        }
    }
}

// =====================================================================
extern "C" void kernel_launch(void* const* d_in, const int* in_sizes, int n_in,
                              void* d_out, int out_size)
{
    const float* s    = (const float*)d_in[0];
    const float* kin  = (const float*)d_in[1];
    const float* mask = (const float*)d_in[2];
    const float* bias = (const float*)d_in[3];
    const float* Wq   = (const float*)d_in[4];
    const float* bq   = (const float*)d_in[5];
    const float* Wk   = (const float*)d_in[6];
    const float* Wv   = (const float*)d_in[7];
    const float* Wg   = (const float*)d_in[8];
    const float* Wo   = (const float*)d_in[9];
    const float* Wz   = (const float*)d_in[10];
    float* out = (float*)d_out;

    cudaFuncSetAttribute(flash_kernel,
                         cudaFuncAttributeMaxDynamicSharedMemorySize, FSMEM);
    cudaFuncSetAttribute(proj_mma,
                         cudaFuncAttributeMaxDynamicSharedMemorySize, GSMEM);
    cudaFuncSetAttribute(out_mma,
                         cudaFuncAttributeMaxDynamicSharedMemorySize, GSMEM);
    cudaFuncSetAttribute(zbias_mma,
                         cudaFuncAttributeMaxDynamicSharedMemorySize, ZSMEM);

    split_kernel<<<dim3(1024, 7), 256>>>(s, kin, Wq, Wk, Wv, Wg, Wo);
    proj_mma    <<<dim3(8, 8, 4),  256, GSMEM>>>(bq);
    zbias_mma   <<<4096,           256, ZSMEM>>>(bias, mask, Wz);
    flash_kernel<<<dim3(32, 16),   256, FSMEM>>>();
    out_mma     <<<dim3(8, 8),     256, GSMEM>>>(out);
}

// round 8
// speedup vs baseline: 1.6174x; 1.6174x over previous
#include <cuda_runtime.h>
#include <cuda_bf16.h>
#include <cuda_fp16.h>
#include <math.h>

#define CS   1024
#define NH   16
#define HD   64
#define SEQ  1024
#define FINF 1e30f

// ---------------- scratch (device globals) ----------------
__device__ float g_g[SEQ * CS];
__device__ __align__(16) __half g_z[(size_t)NH * SEQ * SEQ];   // fp16 logits bias
__constant__ float cWz[128 * 16];

__device__ __align__(16) __nv_bfloat16 b_s_h[SEQ*CS],  b_s_l[SEQ*CS];
__device__ __align__(16) __nv_bfloat16 b_k_h[SEQ*CS],  b_k_l[SEQ*CS];
__device__ __align__(16) __nv_bfloat16 b_Wq_h[CS*CS],  b_Wq_l[CS*CS];
__device__ __align__(16) __nv_bfloat16 b_Wk_h[CS*CS],  b_Wk_l[CS*CS];
__device__ __align__(16) __nv_bfloat16 b_Wv_h[CS*CS],  b_Wv_l[CS*CS];
__device__ __align__(16) __nv_bfloat16 b_Wg_h[CS*CS],  b_Wg_l[CS*CS];
__device__ __align__(16) __nv_bfloat16 b_Wo_h[CS*CS],  b_Wo_l[CS*CS];
__device__ __align__(16) __nv_bfloat16 b_a_h[SEQ*CS],  b_a_l[SEQ*CS];
__device__ __align__(16) __nv_bfloat16 f_q_h[SEQ*CS],  f_q_l[SEQ*CS];
__device__ __align__(16) __nv_bfloat16 f_k_h[SEQ*CS],  f_k_l[SEQ*CS];
__device__ __align__(16) __nv_bfloat16 f_v_h[SEQ*CS],  f_v_l[SEQ*CS];

// ---------------- primitives ----------------
__device__ __forceinline__ void mma_bf16(float d[4], const unsigned a[4], const unsigned b[2]) {
    asm volatile(
        "mma.sync.aligned.m16n8k16.row.col.f32.bf16.bf16.f32 "
        "{%0,%1,%2,%3},{%4,%5,%6,%7},{%8,%9},{%0,%1,%2,%3};\n"
        : "+f"(d[0]), "+f"(d[1]), "+f"(d[2]), "+f"(d[3])
        : "r"(a[0]), "r"(a[1]), "r"(a[2]), "r"(a[3]), "r"(b[0]), "r"(b[1]));
}
__device__ __forceinline__ void ldsm4(unsigned r[4], unsigned addr) {
    asm volatile("ldmatrix.sync.aligned.m8n8.x4.shared.b16 {%0,%1,%2,%3}, [%4];\n"
                 : "=r"(r[0]), "=r"(r[1]), "=r"(r[2]), "=r"(r[3]) : "r"(addr));
}
__device__ __forceinline__ void ldsm2(unsigned r[2], unsigned addr) {
    asm volatile("ldmatrix.sync.aligned.m8n8.x2.shared.b16 {%0,%1}, [%2];\n"
                 : "=r"(r[0]), "=r"(r[1]) : "r"(addr));
}
__device__ __forceinline__ void ldsm2t(unsigned r[2], unsigned addr) {
    asm volatile("ldmatrix.sync.aligned.m8n8.x2.trans.shared.b16 {%0,%1}, [%2];\n"
                 : "=r"(r[0]), "=r"(r[1]) : "r"(addr));
}
__device__ __forceinline__ unsigned smem_u32(const void* p) {
    return (unsigned)__cvta_generic_to_shared(p);
}
__device__ __forceinline__ void cp16(unsigned dst, const void* src) {
    asm volatile("cp.async.cg.shared.global [%0], [%1], 16;\n" :: "r"(dst), "l"(src));
}
__device__ __forceinline__ void cp_commit() {
    asm volatile("cp.async.commit_group;\n" ::: "memory");
}
__device__ __forceinline__ void cp_wait1() {
    asm volatile("cp.async.wait_group 1;\n" ::: "memory");
}
__device__ __forceinline__ void cp_wait0() {
    asm volatile("cp.async.wait_group 0;\n" ::: "memory");
}
__device__ __forceinline__ unsigned packbf(float a, float b) {
    __nv_bfloat162 t = __floats2bfloat162_rn(a, b);
    return *(unsigned*)&t;
}
__device__ __forceinline__ void split1(float x, __nv_bfloat16& h, __nv_bfloat16& l) {
    h = __float2bfloat16_rn(x);
    l = __float2bfloat16_rn(x - __bfloat162float(h));
}
__device__ __forceinline__ void split4_store(float4 v, __nv_bfloat16* ph, __nv_bfloat16* pl) {
    __nv_bfloat16 h0,h1,h2,h3,l0,l1,l2,l3;
    split1(v.x,h0,l0); split1(v.y,h1,l1); split1(v.z,h2,l2); split1(v.w,h3,l3);
    __nv_bfloat162 hh0 = __halves2bfloat162(h0,h1), hh1 = __halves2bfloat162(h2,h3);
    __nv_bfloat162 ll0 = __halves2bfloat162(l0,l1), ll1 = __halves2bfloat162(l2,l3);
    uint2 hu; hu.x = *(unsigned*)&hh0; hu.y = *(unsigned*)&hh1;
    uint2 lu; lu.x = *(unsigned*)&ll0; lu.y = *(unsigned*)&ll1;
    *(uint2*)ph = hu; *(uint2*)pl = lu;
}
__device__ __forceinline__ void split2_store(float a, float b,
                                             __nv_bfloat16* ph, __nv_bfloat16* pl) {
    __nv_bfloat16 h0,h1,l0,l1;
    split1(a,h0,l0); split1(b,h1,l1);
    __nv_bfloat162 hh = __halves2bfloat162(h0,h1);
    __nv_bfloat162 ll = __halves2bfloat162(l0,l1);
    *(unsigned*)ph = *(unsigned*)&hh;
    *(unsigned*)pl = *(unsigned*)&ll;
}

// Kernel S: split the 7 fp32 source matrices into bf16 hi/lo
__global__ __launch_bounds__(256)
void split_kernel(const float* __restrict__ s,  const float* __restrict__ kin,
                  const float* __restrict__ Wq, const float* __restrict__ Wk,
                  const float* __restrict__ Wv, const float* __restrict__ Wg,
                  const float* __restrict__ Wo)
{
    const float* src; __nv_bfloat16 *dh, *dl;
    switch (blockIdx.y) {
        case 0:  src = s;   dh = b_s_h;  dl = b_s_l;  break;
        case 1:  src = kin; dh = b_k_h;  dl = b_k_l;  break;
        case 2:  src = Wq;  dh = b_Wq_h; dl = b_Wq_l; break;
        case 3:  src = Wk;  dh = b_Wk_h; dl = b_Wk_l; break;
        case 4:  src = Wv;  dh = b_Wv_h; dl = b_Wv_l; break;
        case 5:  src = Wg;  dh = b_Wg_h; dl = b_Wg_l; break;
        default: src = Wo;  dh = b_Wo_h; dl = b_Wo_l; break;
    }
    int i = (blockIdx.x * 256 + threadIdx.x) * 4;
    float4 v = *(const float4*)(src + i);
    split4_store(v, dh + i, dl + i);
}

// ---------------- bf16x3 GEMM core, 2-stage cp.async pipeline ----------------
#define LDT 40
#define GST (4*128*LDT)
#define GSMEM (2 * GST * 2)

__device__ __forceinline__ void mma_core(
    const __nv_bfloat16* __restrict__ Ah, const __nv_bfloat16* __restrict__ Al,
    const __nv_bfloat16* __restrict__ Bh, const __nv_bfloat16* __restrict__ Bl,
    int m0, int n0, float acc[4][4][4])
{
    extern __shared__ __nv_bfloat16 gsm[];

    const int tid  = threadIdx.x;
    const int lane = tid & 31;
    const int warp = tid >> 5;
    const int wm   = warp >> 2;
    const int wn   = warp & 3;

    #pragma unroll
    for (int mt = 0; mt < 4; mt++)
        #pragma unroll
        for (int nt = 0; nt < 4; nt++)
            #pragma unroll
            for (int u = 0; u < 4; u++) acc[mt][nt][u] = 0.f;

    const int r0 = tid >> 2,         c0 = (tid & 3) * 8;
    const int r1 = (tid + 256) >> 2;

    const unsigned ub = smem_u32(gsm);
    const unsigned oAl = 128*LDT*2, oBh = 2*128*LDT*2, oBl = 3*128*LDT*2;

    const int amat = lane >> 3, arow = lane & 7;
    const int a_r  = wm * 64 + (amat & 1) * 8 + arow;
    const int a_c  = (amat >> 1) * 8;
    const int b_r  = wn * 32 + arow;
    const int b_c  = ((lane >> 3) & 1) * 8;

    {
        size_t a0 = (size_t)(m0 + r0) * CS + c0, a1 = (size_t)(m0 + r1) * CS + c0;
        size_t b0 = (size_t)(n0 + r0) * CS + c0, b1 = (size_t)(n0 + r1) * CS + c0;
        unsigned s0o = (unsigned)(r0*LDT + c0) * 2, s1o = (unsigned)(r1*LDT + c0) * 2;
        cp16(ub + s0o,       Ah + a0); cp16(ub + s1o,       Ah + a1);
        cp16(ub + oAl + s0o, Al + a0); cp16(ub + oAl + s1o, Al + a1);
        cp16(ub + oBh + s0o, Bh + b0); cp16(ub + oBh + s1o, Bh + b1);
        cp16(ub + oBl + s0o, Bl + b0); cp16(ub + oBl + s1o, Bl + b1);
        cp_commit();
    }

    for (int it = 0; it < 32; it++) {
        const int k0 = it * 32;
        const bool more = (k0 + 32 < CS);
        if (more) {
            const int kn = k0 + 32;
            const unsigned sb = ub + ((it + 1) & 1) * (GST * 2);
            size_t a0 = (size_t)(m0 + r0) * CS + kn + c0, a1 = (size_t)(m0 + r1) * CS + kn + c0;
            size_t b0 = (size_t)(n0 + r0) * CS + kn + c0, b1 = (size_t)(n0 + r1) * CS + kn + c0;
            unsigned s0o = (unsigned)(r0*LDT + c0) * 2, s1o = (unsigned)(r1*LDT + c0) * 2;
            cp16(sb + s0o,       Ah + a0); cp16(sb + s1o,       Ah + a1);
            cp16(sb + oAl + s0o, Al + a0); cp16(sb + oAl + s1o, Al + a1);
            cp16(sb + oBh + s0o, Bh + b0); cp16(sb + oBh + s1o, Bh + b1);
            cp16(sb + oBl + s0o, Bl + b0); cp16(sb + oBl + s1o, Bl + b1);
            cp_commit();
            cp_wait1();
        } else {
            cp_wait0();
        }
        __syncthreads();

        const unsigned sb = ub + (it & 1) * (GST * 2);
        #pragma unroll
        for (int ks = 0; ks < 32; ks += 16) {
            unsigned afh[4][4], afl[4][4], bfh[4][2], bfl[4][2];
            #pragma unroll
            for (int mt = 0; mt < 4; mt++) {
                unsigned off = (unsigned)((a_r + mt*16) * LDT + ks + a_c) * 2;
                ldsm4(afh[mt], sb + off);
                ldsm4(afl[mt], sb + oAl + off);
            }
            #pragma unroll
            for (int nt = 0; nt < 4; nt++) {
                unsigned off = (unsigned)((b_r + nt*8) * LDT + ks + b_c) * 2;
                ldsm2(bfh[nt], sb + oBh + off);
                ldsm2(bfl[nt], sb + oBl + off);
            }
            #pragma unroll
            for (int mt = 0; mt < 4; mt++)
                #pragma unroll
                for (int nt = 0; nt < 4; nt++) {
                    mma_bf16(acc[mt][nt], afh[mt], bfh[nt]);
                    mma_bf16(acc[mt][nt], afh[mt], bfl[nt]);
                    mma_bf16(acc[mt][nt], afl[mt], bfh[nt]);
                }
        }
        __syncthreads();
    }
}

// Kernel 1: projections.  z: 0=q(+bq)->f_q, 1=k->f_k, 2=v->f_v, 3=g(sigmoid)->g_g fp32
__global__ __launch_bounds__(256)
void proj_mma(const float* __restrict__ bq)
{
    const __nv_bfloat16 *Ah, *Al, *Bh, *Bl;
    __nv_bfloat16 *OH = nullptr, *OL = nullptr;
    const float* bias = nullptr;
    switch (blockIdx.z) {
        case 0:  Ah=b_s_h; Al=b_s_l; Bh=b_Wq_h; Bl=b_Wq_l; OH=f_q_h; OL=f_q_l; bias=bq; break;
        case 1:  Ah=b_k_h; Al=b_k_l; Bh=b_Wk_h; Bl=b_Wk_l; OH=f_k_h; OL=f_k_l; break;
        case 2:  Ah=b_k_h; Al=b_k_l; Bh=b_Wv_h; Bl=b_Wv_l; OH=f_v_h; OL=f_v_l; break;
        default: Ah=b_s_h; Al=b_s_l; Bh=b_Wg_h; Bl=b_Wg_l; break;
    }
    const int m0 = blockIdx.y * 128, n0 = blockIdx.x * 128;
    float acc[4][4][4];
    mma_core(Ah, Al, Bh, Bl, m0, n0, acc);

    const int lane = threadIdx.x & 31, warp = threadIdx.x >> 5;
    const int wm = warp >> 2, wn = warp & 3;
    const int lr = lane >> 2, lc = (lane & 3) * 2;
    #pragma unroll
    for (int mt = 0; mt < 4; mt++)
        #pragma unroll
        for (int nt = 0; nt < 4; nt++) {
            int row = m0 + wm*64 + mt*16 + lr;
            int col = n0 + wn*32 + nt*8 + lc;
            float v0 = acc[mt][nt][0], v1 = acc[mt][nt][1];
            float v2 = acc[mt][nt][2], v3 = acc[mt][nt][3];
            if (bias) { float b0_ = bias[col], b1_ = bias[col+1];
                        v0 += b0_; v1 += b1_; v2 += b0_; v3 += b1_; }
            if (blockIdx.z == 3) {
                v0 = 1.0f/(1.0f+__expf(-v0)); v1 = 1.0f/(1.0f+__expf(-v1));
                v2 = 1.0f/(1.0f+__expf(-v2)); v3 = 1.0f/(1.0f+__expf(-v3));
                *(float2*)&g_g[(size_t)row*CS + col]     = make_float2(v0, v1);
                *(float2*)&g_g[(size_t)(row+8)*CS + col] = make_float2(v2, v3);
            } else {
                split2_store(v0, v1, OH + (size_t)row*CS + col,     OL + (size_t)row*CS + col);
                split2_store(v2, v3, OH + (size_t)(row+8)*CS + col, OL + (size_t)(row+8)*CS + col);
            }
        }
}

// Kernel 6: out = (g*o) @ Wo^T
__global__ __launch_bounds__(256)
void out_mma(float* __restrict__ out)
{
    const int m0 = blockIdx.y * 128, n0 = blockIdx.x * 128;
    float acc[4][4][4];
    mma_core(b_a_h, b_a_l, b_Wo_h, b_Wo_l, m0, n0, acc);

    const int lane = threadIdx.x & 31, warp = threadIdx.x >> 5;
    const int wm = warp >> 2, wn = warp & 3;
    const int lr = lane >> 2, lc = (lane & 3) * 2;
    #pragma unroll
    for (int mt = 0; mt < 4; mt++)
        #pragma unroll
        for (int nt = 0; nt < 4; nt++) {
            int row = m0 + wm*64 + mt*16 + lr;
            int col = n0 + wn*32 + nt*8 + lc;
            *(float2*)&out[(size_t)row*CS + col]     = make_float2(acc[mt][nt][0], acc[mt][nt][1]);
            *(float2*)&out[(size_t)(row+8)*CS + col] = make_float2(acc[mt][nt][2], acc[mt][nt][3]);
        }
}

// ---------------- zbias: z[h,i,j] = bias[i,j,:]·Wz[:,h] + mask  (fp16 out) ----------------
__global__ __launch_bounds__(256)
void zbias_kernel(const float* __restrict__ bias, const float* __restrict__ mask)
{
    __shared__ float sb[256][33];
    const int tid = threadIdx.x;
    const long p0 = (long)blockIdx.x * 256;

    float acc[16];
    #pragma unroll
    for (int h = 0; h < 16; h++) acc[h] = 0.f;

    for (int cb = 0; cb < 4; cb++) {
        __syncthreads();
        #pragma unroll
        for (int r = 0; r < 8; r++) {
            int f = tid + r * 256;
            int pair = f >> 3, cq = f & 7;
            float4 v = *(const float4*)&bias[(p0 + pair) * 128 + cb * 32 + cq * 4];
            sb[pair][cq*4+0] = v.x; sb[pair][cq*4+1] = v.y;
            sb[pair][cq*4+2] = v.z; sb[pair][cq*4+3] = v.w;
        }
        __syncthreads();
        #pragma unroll
        for (int c = 0; c < 32; c++) {
            float bvf = sb[tid][c];
            int cg = cb * 32 + c;
            #pragma unroll
            for (int h = 0; h < 16; h++)
                acc[h] += bvf * cWz[cg * 16 + h];
        }
    }
    const long p = p0 + tid;
    const int j = (int)(p & (SEQ - 1));
    // clamp so fp16 stays finite; -60000 still zeroes softmax lanes
    const float madd = (1.0f - mask[j]) * (-1000000.0f);
    #pragma unroll
    for (int h = 0; h < 16; h++) {
        float v = fmaxf(acc[h] + madd, -60000.0f);
        g_z[((long)h << 20) + p] = __float2half_rn(v);
    }
}

// ---------------- flash attention (R4 config + fp16-z prefetch) ----------------
// 64-row q tiles, grid (16,16)=256 blocks, 512 threads = 16 warps:
// wm = warp>>2 (4 row-groups of 16), wj = warp&3 (4 j-quarters of 32).
#define BI 64
#define LQ 72
#define KVST (4 * 128 * LQ)                       // halves per kv stage
#define FSMEM ((2*BI*LQ + 2*KVST) * 2)            // bytes

__global__ __launch_bounds__(512)
void flash_kernel()
{
    extern __shared__ __nv_bfloat16 fsm[];
    __nv_bfloat16* sqh = fsm;
    __nv_bfloat16* sql = sqh + BI*LQ;
    __nv_bfloat16* kvb = sql + BI*LQ;     // [stage][kh, kl, vh, vl] each 128*LQ
    float* cO = (float*)kvb;              // end-of-loop combine overlay

    __shared__ float cm[4][4][16];
    __shared__ float cl[4][4][16];

    const int h  = blockIdx.y;
    const int i0 = blockIdx.x * BI;
    const int tid  = threadIdx.x;
    const int lane = tid & 31;
    const int warp = tid >> 5;
    const int wm = warp >> 2, wj = warp & 3;
    const int lr = lane >> 2, t4 = lane & 3;

    // q tile: 64 x 64 hi/lo; 512 slots per array, 1 each
    {
        int r = tid >> 3, cc = (tid & 7) * 8;
        *(uint4*)&sqh[r*LQ + cc] = *(const uint4*)&f_q_h[(size_t)(i0+r)*CS + h*HD + cc];
        *(uint4*)&sql[r*LQ + cc] = *(const uint4*)&f_q_l[(size_t)(i0+r)*CS + h*HD + cc];
    }

    const unsigned uq  = smem_u32(sqh);
    const unsigned uql = smem_u32(sql);
    const unsigned ukv = smem_u32(kvb);
    const unsigned oKl = 128*LQ*2, oVh = 2*128*LQ*2, oVl = 3*128*LQ*2;

    const unsigned qoff = (unsigned)((wm*16 + (lane & 15)) * LQ + (lane >> 4) * 8) * 2;
    const unsigned koff = (unsigned)((wj*32 + (lane & 7)) * LQ + ((lane >> 3) & 1) * 8) * 2;
    const unsigned voff = (unsigned)((wj*32 + (lane & 7) + ((lane >> 3) & 1) * 8) * LQ) * 2;

    // kv async load: 1024 slots per array / 512 threads = 2 each, 4 arrays
    const int kr0 = tid >> 3,           kc = (tid & 7) * 8;
    const int kr1 = (tid + 512) >> 3;

    float m0 = -FINF, m1 = -FINF, l0 = 0.f, l1 = 0.f;
    float oac[8][4];
    #pragma unroll
    for (int d = 0; d < 8; d++)
        #pragma unroll
        for (int u = 0; u < 4; u++) oac[d][u] = 0.f;

    const __half* Zbase = g_z + ((long)h << 20)
                        + (long)(i0 + wm*16 + lr) * SEQ + wj*32 + t4*2;

    // prologue: stage 0 = tile 0
    {
        unsigned sb = ukv;
        size_t g0 = (size_t)kr0 * CS + h*HD + kc, g1 = (size_t)kr1 * CS + h*HD + kc;
        unsigned s0 = (unsigned)(kr0*LQ + kc)*2, s1 = (unsigned)(kr1*LQ + kc)*2;
        cp16(sb + s0,       f_k_h + g0); cp16(sb + s1,       f_k_h + g1);
        cp16(sb + oKl + s0, f_k_l + g0); cp16(sb + oKl + s1, f_k_l + g1);
        cp16(sb + oVh + s0, f_v_h + g0); cp16(sb + oVh + s1, f_v_h + g1);
        cp16(sb + oVl + s0, f_v_l + g0); cp16(sb + oVl + s1, f_v_l + g1);
        cp_commit();
    }

    for (int jt = 0; jt < 8; jt++) {
        if (jt + 1 < 8) {
            unsigned sb = ukv + ((jt + 1) & 1) * (KVST * 2);
            size_t base = (size_t)((jt + 1) * 128) * CS + h*HD;
            size_t g0 = base + (size_t)kr0 * CS + kc, g1 = base + (size_t)kr1 * CS + kc;
            unsigned s0 = (unsigned)(kr0*LQ + kc)*2, s1 = (unsigned)(kr1*LQ + kc)*2;
            cp16(sb + s0,       f_k_h + g0); cp16(sb + s1,       f_k_h + g1);
            cp16(sb + oKl + s0, f_k_l + g0); cp16(sb + oKl + s1, f_k_l + g1);
            cp16(sb + oVh + s0, f_v_h + g0); cp16(sb + oVh + s1, f_v_h + g1);
            cp16(sb + oVl + s0, f_v_l + g0); cp16(sb + oVl + s1, f_v_l + g1);
            cp_commit();
            cp_wait1();
        } else {
            cp_wait0();
        }
        __syncthreads();

        const unsigned sb = ukv + (jt & 1) * (KVST * 2);

        // prefetch z tile into registers (hidden under QK mma below)
        const __half* Zt = Zbase + jt * 128;
        __half2 zr0[4], zr1[4];
        #pragma unroll
        for (int nt = 0; nt < 4; nt++) {
            zr0[nt] = *(const __half2*)(Zt + nt*8);
            zr1[nt] = *(const __half2*)(Zt + 8*SEQ + nt*8);
        }

        // ---- S = q·k^T over warp's 16 x 32 slice (bf16x3) ----
        float sa[4][4];
        #pragma unroll
        for (int nt = 0; nt < 4; nt++)
            #pragma unroll
            for (int u = 0; u < 4; u++) sa[nt][u] = 0.f;

        #pragma unroll
        for (int ks = 0; ks < 64; ks += 16) {
            unsigned ah[4], al[4];
            ldsm4(ah, uq  + qoff + ks*2);
            ldsm4(al, uql + qoff + ks*2);
            #pragma unroll
            for (int nt = 0; nt < 4; nt++) {
                unsigned bh[2], bl[2];
                unsigned off = koff + (unsigned)(nt*8*LQ + ks) * 2;
                ldsm2(bh, sb + off);
                ldsm2(bl, sb + oKl + off);
                mma_bf16(sa[nt], ah, bh);
                mma_bf16(sa[nt], ah, bl);
                mma_bf16(sa[nt], al, bh);
            }
        }

        // ---- scale + z, online softmax (per warp, over its 32 j) ----
        float mx0 = -FINF, mx1 = -FINF;
        #pragma unroll
        for (int nt = 0; nt < 4; nt++) {
            float2 z0 = __half22float2(zr0[nt]);
            float2 z1 = __half22float2(zr1[nt]);
            sa[nt][0] = sa[nt][0]*0.125f + z0.x;
            sa[nt][1] = sa[nt][1]*0.125f + z0.y;
            sa[nt][2] = sa[nt][2]*0.125f + z1.x;
            sa[nt][3] = sa[nt][3]*0.125f + z1.y;
            mx0 = fmaxf(mx0, fmaxf(sa[nt][0], sa[nt][1]));
            mx1 = fmaxf(mx1, fmaxf(sa[nt][2], sa[nt][3]));
        }
        mx0 = fmaxf(mx0, __shfl_xor_sync(0xffffffffu, mx0, 1));
        mx0 = fmaxf(mx0, __shfl_xor_sync(0xffffffffu, mx0, 2));
        mx1 = fmaxf(mx1, __shfl_xor_sync(0xffffffffu, mx1, 1));
        mx1 = fmaxf(mx1, __shfl_xor_sync(0xffffffffu, mx1, 2));

        float mn0 = fmaxf(m0, mx0), mn1 = fmaxf(m1, mx1);
        float fa0 = __expf(m0 - mn0), fa1 = __expf(m1 - mn1);
        m0 = mn0; m1 = mn1;

        float sum0 = 0.f, sum1 = 0.f;
        #pragma unroll
        for (int nt = 0; nt < 4; nt++) {
            sa[nt][0] = __expf(sa[nt][0] - mn0);
            sa[nt][1] = __expf(sa[nt][1] - mn0);
            sa[nt][2] = __expf(sa[nt][2] - mn1);
            sa[nt][3] = __expf(sa[nt][3] - mn1);
            sum0 += sa[nt][0] + sa[nt][1];
            sum1 += sa[nt][2] + sa[nt][3];
        }
        sum0 += __shfl_xor_sync(0xffffffffu, sum0, 1);
        sum0 += __shfl_xor_sync(0xffffffffu, sum0, 2);
        sum1 += __shfl_xor_sync(0xffffffffu, sum1, 1);
        sum1 += __shfl_xor_sync(0xffffffffu, sum1, 2);
        l0 = l0 * fa0 + sum0;
        l1 = l1 * fa1 + sum1;

        #pragma unroll
        for (int d = 0; d < 8; d++) {
            oac[d][0] *= fa0; oac[d][1] *= fa0;
            oac[d][2] *= fa1; oac[d][3] *= fa1;
        }

        // ---- O += P·V over warp's 32 j (bf16x3) ----
        #pragma unroll
        for (int kt = 0; kt < 2; kt++) {
            float p00 = sa[2*kt][0],   p01 = sa[2*kt][1];
            float p02 = sa[2*kt][2],   p03 = sa[2*kt][3];
            float p10 = sa[2*kt+1][0], p11 = sa[2*kt+1][1];
            float p12 = sa[2*kt+1][2], p13 = sa[2*kt+1][3];

            unsigned pah[4], pal[4];
            pah[0] = packbf(p00, p01); pah[1] = packbf(p02, p03);
            pah[2] = packbf(p10, p11); pah[3] = packbf(p12, p13);
            {
                __nv_bfloat162 t0 = *(__nv_bfloat162*)&pah[0];
                __nv_bfloat162 t1 = *(__nv_bfloat162*)&pah[1];
                __nv_bfloat162 t2 = *(__nv_bfloat162*)&pah[2];
                __nv_bfloat162 t3 = *(__nv_bfloat162*)&pah[3];
                pal[0] = packbf(p00 - __bfloat162float(t0.x), p01 - __bfloat162float(t0.y));
                pal[1] = packbf(p02 - __bfloat162float(t1.x), p03 - __bfloat162float(t1.y));
                pal[2] = packbf(p10 - __bfloat162float(t2.x), p11 - __bfloat162float(t2.y));
                pal[3] = packbf(p12 - __bfloat162float(t3.x), p13 - __bfloat162float(t3.y));
            }

            #pragma unroll
            for (int dnt = 0; dnt < 8; dnt++) {
                unsigned bh[2], bl[2];
                unsigned off = voff + (unsigned)(kt*16*LQ + dnt*8) * 2;
                ldsm2t(bh, sb + oVh + off);
                ldsm2t(bl, sb + oVl + off);
                mma_bf16(oac[dnt], pah, bh);
                mma_bf16(oac[dnt], pah, bl);
                mma_bf16(oac[dnt], pal, bh);
            }
        }
        __syncthreads();
    }

    // ---- merge the 4 j-quarter partials via smem (overlaid on kv region) ----
    {
        float* myO = cO + (size_t)((wm*4 + wj) * 16) * 68;
        #pragma unroll
        for (int dnt = 0; dnt < 8; dnt++) {
            int c = dnt*8 + t4*2;
            myO[lr*68 + c]       = oac[dnt][0];
            myO[lr*68 + c + 1]   = oac[dnt][1];
            myO[(lr+8)*68 + c]   = oac[dnt][2];
            myO[(lr+8)*68 + c+1] = oac[dnt][3];
        }
        if (t4 == 0) {
            cm[wm][wj][lr] = m0;   cl[wm][wj][lr] = l0;
            cm[wm][wj][lr+8] = m1; cl[wm][wj][lr+8] = l1;
        }
    }
    __syncthreads();

    // warp (wm, wj) combines rows of group wm, d-cols [wj*16, wj*16+16)
    {
        const int row = lane >> 1;
        const int db  = wj*16 + (lane & 1) * 8;
        float e[4], M = -FINF;
        #pragma unroll
        for (int w = 0; w < 4; w++) M = fmaxf(M, cm[wm][w][row]);
        float L = 0.f;
        #pragma unroll
        for (int w = 0; w < 4; w++) {
            e[w] = __expf(cm[wm][w][row] - M);
            L += cl[wm][w][row] * e[w];
        }
        const float invL = 1.0f / L;
        const int grow = i0 + wm*16 + row;
        const size_t gbase = (size_t)grow * CS + h*HD;

        #pragma unroll
        for (int p = 0; p < 4; p++) {
            int d = db + p*2;
            float o0 = 0.f, o1 = 0.f;
            #pragma unroll
            for (int w = 0; w < 4; w++) {
                const float* src = cO + (size_t)((wm*4 + w) * 16 + row) * 68 + d;
                o0 += src[0] * e[w];
                o1 += src[1] * e[w];
            }
            float2 gv = *(const float2*)&g_g[gbase + d];
            split2_store(o0 * invL * gv.x, o1 * invL * gv.y,
                         b_a_h + gbase + d, b_a_l + gbase + d);
        }
    }
}

// =====================================================================
extern "C" void kernel_launch(void* const* d_in, const int* in_sizes, int n_in,
                              void* d_out, int out_size)
{
    const float* s    = (const float*)d_in[0];
    const float* kin  = (const float*)d_in[1];
    const float* mask = (const float*)d_in[2];
    const float* bias = (const float*)d_in[3];
    const float* Wq   = (const float*)d_in[4];
    const float* bq   = (const float*)d_in[5];
    const float* Wk   = (const float*)d_in[6];
    const float* Wv   = (const float*)d_in[7];
    const float* Wg   = (const float*)d_in[8];
    const float* Wo   = (const float*)d_in[9];
    const float* Wz   = (const float*)d_in[10];
    float* out = (float*)d_out;

    cudaFuncSetAttribute(flash_kernel,
                         cudaFuncAttributeMaxDynamicSharedMemorySize, FSMEM);
    cudaFuncSetAttribute(proj_mma,
                         cudaFuncAttributeMaxDynamicSharedMemorySize, GSMEM);
    cudaFuncSetAttribute(out_mma,
                         cudaFuncAttributeMaxDynamicSharedMemorySize, GSMEM);

    cudaMemcpyToSymbolAsync(cWz, Wz, 128 * 16 * sizeof(float), 0,
                            cudaMemcpyDeviceToDevice);

    split_kernel<<<dim3(1024, 7), 256>>>(s, kin, Wq, Wk, Wv, Wg, Wo);
    proj_mma    <<<dim3(8, 8, 4),  256, GSMEM>>>(bq);
    zbias_kernel<<<4096,           256>>>(bias, mask);
    flash_kernel<<<dim3(16, 16),   512, FSMEM>>>();
    out_mma     <<<dim3(8, 8),     256, GSMEM>>>(out);
}